// round 1
// baseline (speedup 1.0000x reference)
#include <cuda_runtime.h>
#include <math.h>

#define S_LEN 4096
#define HIDDEN 2048
#define HQ 16
#define HKV 4
#define DHD 128
#define QSTR (HQ*DHD)    // 2048
#define KSTR (HKV*DHD)   // 512
#define RMS_EPS 1e-6f
#define SM_SCALE 0.08838834764831845f  // 128^-0.5

// ------------------------- scratch (static device globals; no runtime alloc) ----
__device__ float g_q[S_LEN * QSTR];
__device__ float g_k[S_LEN * KSTR];
__device__ float g_v[S_LEN * KSTR];
__device__ float g_attn[S_LEN * QSTR];

// ------------------------- fp32 SGEMM: C[M,N] = A[M,K] @ B[K,N] -----------------
// 128x128 tile, BK=8, 256 threads, 8x8 microtile per thread.
__global__ __launch_bounds__(256) void sgemm128(
    const float* __restrict__ A, const float* __restrict__ B, float* __restrict__ C,
    int M, int N, int K)
{
    __shared__ float As[8 * 128];   // stored transposed: As[kk][m]
    __shared__ float Bs[8 * 128];   // Bs[kk][n]

    const int tid   = threadIdx.x;
    const int mBase = blockIdx.y * 128;
    const int nBase = blockIdx.x * 128;
    const int ty = tid >> 4;        // 0..15
    const int tx = tid & 15;        // 0..15
    const int m0 = ty * 8;
    const int n0 = tx * 8;

    // global-load assignments
    const int lm = tid >> 1;          // 0..127 (A row in tile)
    const int lk = (tid & 1) * 4;     // 0 or 4 (A k-offset)
    const int bk = tid >> 5;          // 0..7   (B k row)
    const int bn = (tid & 31) * 4;    // 0..124 (B col)

    float acc[8][8];
#pragma unroll
    for (int i = 0; i < 8; i++)
#pragma unroll
        for (int j = 0; j < 8; j++) acc[i][j] = 0.f;

    for (int k0 = 0; k0 < K; k0 += 8) {
        float4 av = *(const float4*)(A + (size_t)(mBase + lm) * K + k0 + lk);
        float4 bv = *(const float4*)(B + (size_t)(k0 + bk) * N + nBase + bn);
        __syncthreads();   // previous iteration's compute done before overwrite
        As[(lk + 0) * 128 + lm] = av.x;
        As[(lk + 1) * 128 + lm] = av.y;
        As[(lk + 2) * 128 + lm] = av.z;
        As[(lk + 3) * 128 + lm] = av.w;
        *(float4*)(Bs + bk * 128 + bn) = bv;
        __syncthreads();

#pragma unroll
        for (int kk = 0; kk < 8; kk++) {
            float a[8], b[8];
            *(float4*)(a)     = *(const float4*)(As + kk * 128 + m0);
            *(float4*)(a + 4) = *(const float4*)(As + kk * 128 + m0 + 4);
            *(float4*)(b)     = *(const float4*)(Bs + kk * 128 + n0);
            *(float4*)(b + 4) = *(const float4*)(Bs + kk * 128 + n0 + 4);
#pragma unroll
            for (int i = 0; i < 8; i++)
#pragma unroll
                for (int j = 0; j < 8; j++) acc[i][j] = fmaf(a[i], b[j], acc[i][j]);
        }
    }

#pragma unroll
    for (int i = 0; i < 8; i++) {
        float* crow = C + (size_t)(mBase + m0 + i) * N + nBase + n0;
        *(float4*)(crow)     = *(float4*)(acc[i]);
        *(float4*)(crow + 4) = *(float4*)(acc[i] + 4);
    }
}

// ------------------------- fused RMSNorm + RoPE (in place) ----------------------
// grid (S, nHeads), block 128. One block normalizes one (s, head) row of 128,
// then applies rotary embedding. outScale folds the attention score scaling.
__global__ __launch_bounds__(128) void rmsnorm_rope(
    float* __restrict__ buf, const float* __restrict__ cosp, const float* __restrict__ sinp,
    const float* __restrict__ w, int rowStride, float outScale)
{
    const int s = blockIdx.x;
    const int h = blockIdx.y;
    const int d = threadIdx.x;

    float* x = buf + (size_t)s * rowStride + h * DHD;
    float v = x[d];

    __shared__ float red[128];
    red[d] = v * v;
    __syncthreads();
#pragma unroll
    for (int off = 64; off > 0; off >>= 1) {
        if (d < off) red[d] += red[d + off];
        __syncthreads();
    }
    float inv = rsqrtf(red[0] * (1.0f / DHD) + RMS_EPS);

    const int dp = (d < 64) ? d + 64 : d - 64;
    float vp  = x[dp];
    float xn  = v  * inv * w[d];
    float xpn = vp * inv * w[dp];
    float c  = cosp[s * DHD + d];
    float sn = sinp[s * DHD + d];
    float rot = (d < 64) ? -xpn : xpn;
    float out = (xn * c + rot * sn) * outScale;
    __syncthreads();   // all reads of x done before any write
    x[d] = out;
}

// ------------------------- causal flash attention (fp32) ------------------------
// CTA: 64 queries x 1 head, 256 threads. Streams 64-key tiles up to the diagonal.
#define BM 64
#define BN 64
#define QPAD 132     // row stride for 128-wide tiles (conflict padding, 16B aligned)
#define SPAD 65

__global__ __launch_bounds__(256) void flash_attn(
    const float* __restrict__ Q, const float* __restrict__ K, const float* __restrict__ V,
    float* __restrict__ O)
{
    extern __shared__ float sm[];
    float* Qs   = sm;                       // BM x QPAD
    float* Ks   = Qs + BM * QPAD;           // BN x QPAD
    float* Vs   = Ks + BN * QPAD;           // BN x QPAD
    float* Ss   = Vs + BN * QPAD;           // BM x SPAD
    float* mrow = Ss + BM * SPAD;           // BM
    float* lrow = mrow + BM;                // BM
    float* arow = lrow + BM;                // BM

    const int tid = threadIdx.x;
    const int qt  = blockIdx.x;             // query tile
    const int h   = blockIdx.y;             // query head
    const int hk  = h >> 2;                 // kv head (GQA 4:1)
    const int qm0 = qt * BM;
    const int ty = tid >> 4, tx = tid & 15;
    const int r0  = ty * 4;                 // 4 query rows per thread
    const int cS0 = tx * 4;                 // 4 score cols per thread
    const int cO0 = tx * 8;                 // 8 output dims per thread

    // load Q tile (64 x 128)
    for (int i = tid; i < BM * 32; i += 256) {
        int r = i >> 5, d4 = (i & 31) * 4;
        *(float4*)(Qs + r * QPAD + d4) =
            *(const float4*)(Q + (size_t)(qm0 + r) * QSTR + h * DHD + d4);
    }
    if (tid < BM) { mrow[tid] = -3.0e38f; lrow[tid] = 0.f; }

    float o[4][8];
#pragma unroll
    for (int i = 0; i < 4; i++)
#pragma unroll
        for (int j = 0; j < 8; j++) o[i][j] = 0.f;
    __syncthreads();

    for (int t = 0; t <= qt; t++) {
        const int kg0 = t * BN;
        // load K/V tiles
        for (int i = tid; i < BN * 32; i += 256) {
            int r = i >> 5, d4 = (i & 31) * 4;
            *(float4*)(Ks + r * QPAD + d4) =
                *(const float4*)(K + (size_t)(kg0 + r) * KSTR + hk * DHD + d4);
            *(float4*)(Vs + r * QPAD + d4) =
                *(const float4*)(V + (size_t)(kg0 + r) * KSTR + hk * DHD + d4);
        }
        __syncthreads();

        // scores: S = Q @ K^T (64x64, K=128)
        float acc[4][4];
#pragma unroll
        for (int i = 0; i < 4; i++)
#pragma unroll
            for (int j = 0; j < 4; j++) acc[i][j] = 0.f;
#pragma unroll 4
        for (int kk = 0; kk < DHD; kk++) {
            float qa[4], kb[4];
#pragma unroll
            for (int i = 0; i < 4; i++) qa[i] = Qs[(r0 + i) * QPAD + kk];
#pragma unroll
            for (int j = 0; j < 4; j++) kb[j] = Ks[(cS0 + j) * QPAD + kk];
#pragma unroll
            for (int i = 0; i < 4; i++)
#pragma unroll
                for (int j = 0; j < 4; j++) acc[i][j] = fmaf(qa[i], kb[j], acc[i][j]);
        }
        const bool diag = (t == qt);
#pragma unroll
        for (int i = 0; i < 4; i++)
#pragma unroll
            for (int j = 0; j < 4; j++) {
                float sv = acc[i][j];
                if (diag && (kg0 + cS0 + j > qm0 + r0 + i)) sv = -1.0e30f;
                Ss[(r0 + i) * SPAD + cS0 + j] = sv;
            }
        __syncthreads();

        // online softmax per row (threads 0..63 each own a row)
        if (tid < BM) {
            float mold = mrow[tid];
            float mx = mold;
            const float* srow = Ss + tid * SPAD;
#pragma unroll 8
            for (int j = 0; j < BN; j++) mx = fmaxf(mx, srow[j]);
            float alpha = __expf(mold - mx);
            float sum = 0.f;
            float* srw = Ss + tid * SPAD;
#pragma unroll 8
            for (int j = 0; j < BN; j++) {
                float p = __expf(srw[j] - mx);
                srw[j] = p;
                sum += p;
            }
            mrow[tid] = mx;
            lrow[tid] = lrow[tid] * alpha + sum;
            arow[tid] = alpha;
        }
        __syncthreads();

        // O = O*alpha + P @ V
        float al[4];
#pragma unroll
        for (int i = 0; i < 4; i++) al[i] = arow[r0 + i];
#pragma unroll
        for (int i = 0; i < 4; i++)
#pragma unroll
            for (int j = 0; j < 8; j++) o[i][j] *= al[i];
#pragma unroll 2
        for (int kk = 0; kk < BN; kk++) {
            float pa[4], vb[8];
#pragma unroll
            for (int i = 0; i < 4; i++) pa[i] = Ss[(r0 + i) * SPAD + kk];
#pragma unroll
            for (int j = 0; j < 8; j++) vb[j] = Vs[kk * QPAD + cO0 + j];
#pragma unroll
            for (int i = 0; i < 4; i++)
#pragma unroll
                for (int j = 0; j < 8; j++) o[i][j] = fmaf(pa[i], vb[j], o[i][j]);
        }
        __syncthreads();   // before next tile overwrites K/V/S
    }

    // epilogue: divide by l, write to attn buffer in (s, h*128+d) layout
#pragma unroll
    for (int i = 0; i < 4; i++) {
        float invl = 1.0f / lrow[r0 + i];
        float* orow = O + (size_t)(qm0 + r0 + i) * QSTR + h * DHD + cO0;
#pragma unroll
        for (int j = 0; j < 8; j++) orow[j] = o[i][j] * invl;
    }
}

// ------------------------- launch -----------------------------------------------
extern "C" void kernel_launch(void* const* d_in, const int* in_sizes, int n_in,
                              void* d_out, int out_size)
{
    (void)in_sizes; (void)n_in; (void)out_size;
    const float* hs   = (const float*)d_in[0];
    const float* cosp = (const float*)d_in[1];
    const float* sinp = (const float*)d_in[2];
    const float* wq   = (const float*)d_in[3];
    const float* wk   = (const float*)d_in[4];
    const float* wv   = (const float*)d_in[5];
    const float* wo   = (const float*)d_in[6];
    const float* qnw  = (const float*)d_in[7];
    const float* knw  = (const float*)d_in[8];
    float* out = (float*)d_out;

    float *qp, *kp, *vp, *ap;
    cudaGetSymbolAddress((void**)&qp, g_q);
    cudaGetSymbolAddress((void**)&kp, g_k);
    cudaGetSymbolAddress((void**)&vp, g_v);
    cudaGetSymbolAddress((void**)&ap, g_attn);

    static const int FA_SMEM = (3 * BM * QPAD + BM * SPAD + 3 * BM) * (int)sizeof(float);
    cudaFuncSetAttribute(flash_attn, cudaFuncAttributeMaxDynamicSharedMemorySize, FA_SMEM);

    // 1-3) QKV projections
    sgemm128<<<dim3(QSTR / 128, S_LEN / 128), 256>>>(hs, wq, qp, S_LEN, QSTR, HIDDEN);
    sgemm128<<<dim3(KSTR / 128, S_LEN / 128), 256>>>(hs, wk, kp, S_LEN, KSTR, HIDDEN);
    sgemm128<<<dim3(KSTR / 128, S_LEN / 128), 256>>>(hs, wv, vp, S_LEN, KSTR, HIDDEN);

    // 4-5) RMSNorm + RoPE (score scale folded into Q)
    rmsnorm_rope<<<dim3(S_LEN, HQ), 128>>>(qp, cosp, sinp, qnw, QSTR, SM_SCALE);
    rmsnorm_rope<<<dim3(S_LEN, HKV), 128>>>(kp, cosp, sinp, knw, KSTR, 1.0f);

    // 6) causal flash attention
    flash_attn<<<dim3(S_LEN / BM, HQ), 256, FA_SMEM>>>(qp, kp, vp, ap);

    // 7) output projection
    sgemm128<<<dim3(HIDDEN / 128, S_LEN / 128), 256>>>(ap, wo, out, S_LEN, HIDDEN, HIDDEN);
}

// round 3
// speedup vs baseline: 1.2682x; 1.2682x over previous
#include <cuda_runtime.h>
#include <cuda_bf16.h>
#include <math.h>
#include <stdint.h>

#define S_LEN 4096
#define HIDDEN 2048
#define HQ 16
#define HKV 4
#define DHD 128
#define QSTR (HQ*DHD)    // 2048
#define KSTR (HKV*DHD)   // 512
#define RMS_EPS 1e-6f
#define SM_SCALE 0.08838834764831845f  // 128^-0.5

// ------------------------- scratch (static device globals) ----------------------
__device__ float g_q[S_LEN * QSTR];
__device__ float g_k[S_LEN * KSTR];
__device__ float g_v[S_LEN * KSTR];
__device__ float g_attn[S_LEN * QSTR];

// bf16 split buffers
__device__ __nv_bfloat16 g_hs_h[S_LEN * HIDDEN];
__device__ __nv_bfloat16 g_hs_l[S_LEN * HIDDEN];
__device__ __nv_bfloat16 g_at_h[S_LEN * QSTR];
__device__ __nv_bfloat16 g_at_l[S_LEN * QSTR];
// transposed weights [N, K]
__device__ __nv_bfloat16 g_wq_h[QSTR * HIDDEN];
__device__ __nv_bfloat16 g_wq_l[QSTR * HIDDEN];
__device__ __nv_bfloat16 g_wk_h[KSTR * HIDDEN];
__device__ __nv_bfloat16 g_wk_l[KSTR * HIDDEN];
__device__ __nv_bfloat16 g_wv_h[KSTR * HIDDEN];
__device__ __nv_bfloat16 g_wv_l[KSTR * HIDDEN];
__device__ __nv_bfloat16 g_wo_h[HIDDEN * QSTR];
__device__ __nv_bfloat16 g_wo_l[HIDDEN * QSTR];

// ------------------------- helpers ----------------------------------------------
__device__ __forceinline__ uint32_t smem_u32(const void* p) {
    uint32_t a;
    asm("{ .reg .u64 t; cvta.to.shared.u64 t, %1; cvt.u32.u64 %0, t; }" : "=r"(a) : "l"(p));
    return a;
}
__device__ __forceinline__ void ldsm_x4(uint32_t* r, uint32_t addr) {
    asm volatile("ldmatrix.sync.aligned.m8n8.x4.shared.b16 {%0,%1,%2,%3}, [%4];"
                 : "=r"(r[0]), "=r"(r[1]), "=r"(r[2]), "=r"(r[3]) : "r"(addr));
}
__device__ __forceinline__ void mma_bf16(float* d, const uint32_t* a, const uint32_t* b,
                                         const float* c) {
    asm volatile(
        "mma.sync.aligned.m16n8k16.row.col.f32.bf16.bf16.f32 "
        "{%0,%1,%2,%3}, {%4,%5,%6,%7}, {%8,%9}, {%10,%11,%12,%13};"
        : "=f"(d[0]), "=f"(d[1]), "=f"(d[2]), "=f"(d[3])
        : "r"(a[0]), "r"(a[1]), "r"(a[2]), "r"(a[3]),
          "r"(b[0]), "r"(b[1]),
          "f"(c[0]), "f"(c[1]), "f"(c[2]), "f"(c[3]));
}
__device__ __forceinline__ void cp_async16(uint32_t dst, const void* src) {
    asm volatile("cp.async.cg.shared.global [%0], [%1], 16;" :: "r"(dst), "l"(src) : "memory");
}
__device__ __forceinline__ void cp_commit() {
    asm volatile("cp.async.commit_group;" ::: "memory");
}
// smem tile layout: 128 rows x 32 bf16 (64B/row); physical 128B rows with XOR swizzle
__device__ __forceinline__ uint32_t swz(uint32_t tileBase, int r, int c) {
    uint32_t off = r * 64 + c * 16;
    off ^= ((off >> 7) & 7) << 4;
    return tileBase + off;
}

// ------------------------- fp32 -> bf16 hi/lo split ------------------------------
__global__ __launch_bounds__(256) void conv_split(
    const float* __restrict__ X, __nv_bfloat16* __restrict__ H,
    __nv_bfloat16* __restrict__ L)
{
    int i = (blockIdx.x * 256 + threadIdx.x) * 4;
    float4 v = *(const float4*)(X + i);
    __nv_bfloat16 h0 = __float2bfloat16(v.x), h1 = __float2bfloat16(v.y);
    __nv_bfloat16 h2 = __float2bfloat16(v.z), h3 = __float2bfloat16(v.w);
    __nv_bfloat16 l0 = __float2bfloat16(v.x - __bfloat162float(h0));
    __nv_bfloat16 l1 = __float2bfloat16(v.y - __bfloat162float(h1));
    __nv_bfloat16 l2 = __float2bfloat16(v.z - __bfloat162float(h2));
    __nv_bfloat16 l3 = __float2bfloat16(v.w - __bfloat162float(h3));
    *(__nv_bfloat162*)(H + i)     = __halves2bfloat162(h0, h1);
    *(__nv_bfloat162*)(H + i + 2) = __halves2bfloat162(h2, h3);
    *(__nv_bfloat162*)(L + i)     = __halves2bfloat162(l0, l1);
    *(__nv_bfloat162*)(L + i + 2) = __halves2bfloat162(l2, l3);
}

// ------------------------- fp32 [K,N] -> bf16 hi/lo transposed [N,K] -------------
__global__ __launch_bounds__(256) void conv_w_t(
    const float* __restrict__ W, __nv_bfloat16* __restrict__ Th,
    __nv_bfloat16* __restrict__ Tl, int K, int N)
{
    __shared__ float t[32][33];
    int n0 = blockIdx.x * 32, k0 = blockIdx.y * 32;
    int tx = threadIdx.x & 31, ty = threadIdx.x >> 5;  // 32 x 8
#pragma unroll
    for (int j = 0; j < 4; j++)
        t[ty + 8 * j][tx] = W[(size_t)(k0 + ty + 8 * j) * N + n0 + tx];
    __syncthreads();
#pragma unroll
    for (int j = 0; j < 4; j++) {
        float v = t[tx][ty + 8 * j];
        __nv_bfloat16 h = __float2bfloat16(v);
        size_t o = (size_t)(n0 + ty + 8 * j) * K + k0 + tx;
        Th[o] = h;
        Tl[o] = __float2bfloat16(v - __bfloat162float(h));
    }
}

// ------------------------- bf16x3 HMMA GEMM --------------------------------------
// C[M,N] fp32 = (Ah+Al)[M,K] @ (Bh+Bl)[N,K]^T, dropping lo*lo.
// CTA 128x128, K-chunk 32, 8 warps (4M x 2N), warp tile 32x64, double-buffered.
#define GT_BYTES 8192                       // one 128x32 bf16 tile
#define GSTAGE   (4 * GT_BYTES)             // Ah, Al, Bh, Bl
#define G_SMEM   (2 * GSTAGE)               // double buffer (64 KB)

__global__ __launch_bounds__(256) void gemm_bf16x3(
    const __nv_bfloat16* __restrict__ Ah, const __nv_bfloat16* __restrict__ Al,
    const __nv_bfloat16* __restrict__ Bh, const __nv_bfloat16* __restrict__ Bl,
    float* __restrict__ C, int M, int N, int K)
{
    extern __shared__ char smc[];
    const uint32_t sb = smem_u32(smc);
    const int tid  = threadIdx.x;
    const int wid  = tid >> 5;
    const int lane = tid & 31;
    const int m0 = blockIdx.y * 128, n0 = blockIdx.x * 128;
    const int mBase = (wid >> 1) * 32;      // warp row offset in tile
    const int nBase = (wid & 1) * 64;       // warp col offset in tile

    const __nv_bfloat16* srcs[4] = {Ah + (size_t)m0 * K, Al + (size_t)m0 * K,
                                    Bh + (size_t)n0 * K, Bl + (size_t)n0 * K};

    // per-thread cp.async slots: i = tid + 256*s ; tile=i>>9, r=(i>>2)&127, c=i&3
    float acc[2][8][4];
#pragma unroll
    for (int f = 0; f < 2; f++)
#pragma unroll
        for (int j = 0; j < 8; j++)
#pragma unroll
            for (int x = 0; x < 4; x++) acc[f][j][x] = 0.f;

    const int nChunks = K >> 5;

    // prologue: stage 0
    {
        const int k0 = 0;
#pragma unroll
        for (int s = 0; s < 8; s++) {
            int i = tid + 256 * s;
            int tile = i >> 9, r = (i >> 2) & 127, c = i & 3;
            cp_async16(swz(sb + tile * GT_BYTES, r, c),
                       srcs[tile] + (size_t)r * K + k0 + c * 8);
        }
        cp_commit();
    }

    const int lr = lane & 15, lc = lane >> 4;

    for (int kc = 0; kc < nChunks; kc++) {
        const uint32_t st = sb + (kc & 1) * GSTAGE;
        if (kc + 1 < nChunks) {
            const int k0 = (kc + 1) << 5;
            const uint32_t stn = sb + ((kc + 1) & 1) * GSTAGE;
#pragma unroll
            for (int s = 0; s < 8; s++) {
                int i = tid + 256 * s;
                int tile = i >> 9, r = (i >> 2) & 127, c = i & 3;
                cp_async16(swz(stn + tile * GT_BYTES, r, c),
                           srcs[tile] + (size_t)r * K + k0 + c * 8);
            }
            cp_commit();
            asm volatile("cp.async.wait_group 1;" ::: "memory");
        } else {
            asm volatile("cp.async.wait_group 0;" ::: "memory");
        }
        __syncthreads();

        const uint32_t tAh = st, tAl = st + GT_BYTES;
        const uint32_t tBh = st + 2 * GT_BYTES, tBl = st + 3 * GT_BYTES;

#pragma unroll
        for (int ks = 0; ks < 2; ks++) {
            const int ch = ks * 2 + lc;
            uint32_t ah[2][4], al[2][4], bb[4][4];
            // A hi frags (2 x m16)
#pragma unroll
            for (int f = 0; f < 2; f++)
                ldsm_x4(ah[f], swz(tAh, mBase + f * 16 + lr, ch));
            // B hi frags (4 x n16 -> 8 x n8)
#pragma unroll
            for (int g = 0; g < 4; g++)
                ldsm_x4(bb[g], swz(tBh, nBase + g * 16 + lr, ch));
            // hi*hi
#pragma unroll
            for (int f = 0; f < 2; f++)
#pragma unroll
                for (int j = 0; j < 8; j++) {
                    uint32_t bfr[2] = {bb[j >> 1][j & 1], bb[j >> 1][2 + (j & 1)]};
                    mma_bf16(acc[f][j], ah[f], bfr, acc[f][j]);
                }
            // A lo frags, lo*hi
#pragma unroll
            for (int f = 0; f < 2; f++)
                ldsm_x4(al[f], swz(tAl, mBase + f * 16 + lr, ch));
#pragma unroll
            for (int f = 0; f < 2; f++)
#pragma unroll
                for (int j = 0; j < 8; j++) {
                    uint32_t bfr[2] = {bb[j >> 1][j & 1], bb[j >> 1][2 + (j & 1)]};
                    mma_bf16(acc[f][j], al[f], bfr, acc[f][j]);
                }
            // B lo frags, hi*lo
#pragma unroll
            for (int g = 0; g < 4; g++)
                ldsm_x4(bb[g], swz(tBl, nBase + g * 16 + lr, ch));
#pragma unroll
            for (int f = 0; f < 2; f++)
#pragma unroll
                for (int j = 0; j < 8; j++) {
                    uint32_t bfr[2] = {bb[j >> 1][j & 1], bb[j >> 1][2 + (j & 1)]};
                    mma_bf16(acc[f][j], ah[f], bfr, acc[f][j]);
                }
        }
        __syncthreads();
    }

    // epilogue: d0,d1 -> (row, col..col+1), d2,d3 -> (row+8, col..col+1)
    const int erow = lane >> 2;
    const int ecol = (lane & 3) * 2;
#pragma unroll
    for (int f = 0; f < 2; f++) {
        int rg = m0 + mBase + f * 16 + erow;
#pragma unroll
        for (int j = 0; j < 8; j++) {
            int cg = n0 + nBase + j * 8 + ecol;
            *(float2*)(C + (size_t)rg * N + cg)       = make_float2(acc[f][j][0], acc[f][j][1]);
            *(float2*)(C + (size_t)(rg + 8) * N + cg) = make_float2(acc[f][j][2], acc[f][j][3]);
        }
    }
}

// ------------------------- fused RMSNorm + RoPE (in place) ----------------------
__global__ __launch_bounds__(128) void rmsnorm_rope(
    float* __restrict__ buf, const float* __restrict__ cosp, const float* __restrict__ sinp,
    const float* __restrict__ w, int rowStride, float outScale)
{
    const int s = blockIdx.x;
    const int h = blockIdx.y;
    const int d = threadIdx.x;

    float* x = buf + (size_t)s * rowStride + h * DHD;
    float v = x[d];

    __shared__ float red[128];
    red[d] = v * v;
    __syncthreads();
#pragma unroll
    for (int off = 64; off > 0; off >>= 1) {
        if (d < off) red[d] += red[d + off];
        __syncthreads();
    }
    float inv = rsqrtf(red[0] * (1.0f / DHD) + RMS_EPS);

    const int dp = (d < 64) ? d + 64 : d - 64;
    float vp  = x[dp];
    float xn  = v  * inv * w[d];
    float xpn = vp * inv * w[dp];
    float c  = cosp[s * DHD + d];
    float sn = sinp[s * DHD + d];
    float rot = (d < 64) ? -xpn : xpn;
    float out = (xn * c + rot * sn) * outScale;
    __syncthreads();
    x[d] = out;
}

// ------------------------- causal flash attention (fp32) ------------------------
#define BM 64
#define BN 64
#define QPAD 132
#define SPAD 65

__global__ __launch_bounds__(256) void flash_attn(
    const float* __restrict__ Q, const float* __restrict__ K, const float* __restrict__ V,
    float* __restrict__ O)
{
    extern __shared__ float smf[];
    float* Qs   = smf;
    float* Ks   = Qs + BM * QPAD;
    float* Vs   = Ks + BN * QPAD;
    float* Ss   = Vs + BN * QPAD;
    float* mrow = Ss + BM * SPAD;
    float* lrow = mrow + BM;
    float* arow = lrow + BM;

    const int tid = threadIdx.x;
    const int qt  = blockIdx.x;
    const int h   = blockIdx.y;
    const int hk  = h >> 2;
    const int qm0 = qt * BM;
    const int ty = tid >> 4, tx = tid & 15;
    const int r0  = ty * 4;
    const int cS0 = tx * 4;
    const int cO0 = tx * 8;

    for (int i = tid; i < BM * 32; i += 256) {
        int r = i >> 5, d4 = (i & 31) * 4;
        *(float4*)(Qs + r * QPAD + d4) =
            *(const float4*)(Q + (size_t)(qm0 + r) * QSTR + h * DHD + d4);
    }
    if (tid < BM) { mrow[tid] = -3.0e38f; lrow[tid] = 0.f; }

    float o[4][8];
#pragma unroll
    for (int i = 0; i < 4; i++)
#pragma unroll
        for (int j = 0; j < 8; j++) o[i][j] = 0.f;
    __syncthreads();

    for (int t = 0; t <= qt; t++) {
        const int kg0 = t * BN;
        for (int i = tid; i < BN * 32; i += 256) {
            int r = i >> 5, d4 = (i & 31) * 4;
            *(float4*)(Ks + r * QPAD + d4) =
                *(const float4*)(K + (size_t)(kg0 + r) * KSTR + hk * DHD + d4);
            *(float4*)(Vs + r * QPAD + d4) =
                *(const float4*)(V + (size_t)(kg0 + r) * KSTR + hk * DHD + d4);
        }
        __syncthreads();

        float acc[4][4];
#pragma unroll
        for (int i = 0; i < 4; i++)
#pragma unroll
            for (int j = 0; j < 4; j++) acc[i][j] = 0.f;
#pragma unroll 4
        for (int kk = 0; kk < DHD; kk++) {
            float qa[4], kb[4];
#pragma unroll
            for (int i = 0; i < 4; i++) qa[i] = Qs[(r0 + i) * QPAD + kk];
#pragma unroll
            for (int j = 0; j < 4; j++) kb[j] = Ks[(cS0 + j) * QPAD + kk];
#pragma unroll
            for (int i = 0; i < 4; i++)
#pragma unroll
                for (int j = 0; j < 4; j++) acc[i][j] = fmaf(qa[i], kb[j], acc[i][j]);
        }
        const bool diag = (t == qt);
#pragma unroll
        for (int i = 0; i < 4; i++)
#pragma unroll
            for (int j = 0; j < 4; j++) {
                float sv = acc[i][j];
                if (diag && (kg0 + cS0 + j > qm0 + r0 + i)) sv = -1.0e30f;
                Ss[(r0 + i) * SPAD + cS0 + j] = sv;
            }
        __syncthreads();

        if (tid < BM) {
            float mold = mrow[tid];
            float mx = mold;
            const float* srow = Ss + tid * SPAD;
#pragma unroll 8
            for (int j = 0; j < BN; j++) mx = fmaxf(mx, srow[j]);
            float alpha = __expf(mold - mx);
            float sum = 0.f;
            float* srw = Ss + tid * SPAD;
#pragma unroll 8
            for (int j = 0; j < BN; j++) {
                float p = __expf(srw[j] - mx);
                srw[j] = p;
                sum += p;
            }
            mrow[tid] = mx;
            lrow[tid] = lrow[tid] * alpha + sum;
            arow[tid] = alpha;
        }
        __syncthreads();

        float al[4];
#pragma unroll
        for (int i = 0; i < 4; i++) al[i] = arow[r0 + i];
#pragma unroll
        for (int i = 0; i < 4; i++)
#pragma unroll
            for (int j = 0; j < 8; j++) o[i][j] *= al[i];
#pragma unroll 2
        for (int kk = 0; kk < BN; kk++) {
            float pa[4], vb[8];
#pragma unroll
            for (int i = 0; i < 4; i++) pa[i] = Ss[(r0 + i) * SPAD + kk];
#pragma unroll
            for (int j = 0; j < 8; j++) vb[j] = Vs[kk * QPAD + cO0 + j];
#pragma unroll
            for (int i = 0; i < 4; i++)
#pragma unroll
                for (int j = 0; j < 8; j++) o[i][j] = fmaf(pa[i], vb[j], o[i][j]);
        }
        __syncthreads();
    }

#pragma unroll
    for (int i = 0; i < 4; i++) {
        float invl = 1.0f / lrow[r0 + i];
        float* orow = O + (size_t)(qm0 + r0 + i) * QSTR + h * DHD + cO0;
#pragma unroll
        for (int j = 0; j < 8; j++) orow[j] = o[i][j] * invl;
    }
}

// ------------------------- launch -----------------------------------------------
extern "C" void kernel_launch(void* const* d_in, const int* in_sizes, int n_in,
                              void* d_out, int out_size)
{
    (void)in_sizes; (void)n_in; (void)out_size;
    const float* hs   = (const float*)d_in[0];
    const float* cosp = (const float*)d_in[1];
    const float* sinp = (const float*)d_in[2];
    const float* wq   = (const float*)d_in[3];
    const float* wk   = (const float*)d_in[4];
    const float* wv   = (const float*)d_in[5];
    const float* wo   = (const float*)d_in[6];
    const float* qnw  = (const float*)d_in[7];
    const float* knw  = (const float*)d_in[8];
    float* out = (float*)d_out;

    float *qp, *kp, *vp, *ap;
    cudaGetSymbolAddress((void**)&qp, g_q);
    cudaGetSymbolAddress((void**)&kp, g_k);
    cudaGetSymbolAddress((void**)&vp, g_v);
    cudaGetSymbolAddress((void**)&ap, g_attn);
    __nv_bfloat16 *hsh, *hsl, *ath, *atl;
    __nv_bfloat16 *wqh, *wql, *wkh, *wkl, *wvh, *wvl, *woh, *wol;
    cudaGetSymbolAddress((void**)&hsh, g_hs_h);
    cudaGetSymbolAddress((void**)&hsl, g_hs_l);
    cudaGetSymbolAddress((void**)&ath, g_at_h);
    cudaGetSymbolAddress((void**)&atl, g_at_l);
    cudaGetSymbolAddress((void**)&wqh, g_wq_h);
    cudaGetSymbolAddress((void**)&wql, g_wq_l);
    cudaGetSymbolAddress((void**)&wkh, g_wk_h);
    cudaGetSymbolAddress((void**)&wkl, g_wk_l);
    cudaGetSymbolAddress((void**)&wvh, g_wv_h);
    cudaGetSymbolAddress((void**)&wvl, g_wv_l);
    cudaGetSymbolAddress((void**)&woh, g_wo_h);
    cudaGetSymbolAddress((void**)&wol, g_wo_l);

    static const int FA_SMEM = (3 * BM * QPAD + BM * SPAD + 3 * BM) * (int)sizeof(float);
    cudaFuncSetAttribute(flash_attn, cudaFuncAttributeMaxDynamicSharedMemorySize, FA_SMEM);
    cudaFuncSetAttribute(gemm_bf16x3, cudaFuncAttributeMaxDynamicSharedMemorySize, G_SMEM);

    // 0) precision splits + weight transposes
    conv_split<<<(S_LEN * HIDDEN) / 1024, 256>>>(hs, hsh, hsl);
    conv_w_t<<<dim3(QSTR / 32, HIDDEN / 32), 256>>>(wq, wqh, wql, HIDDEN, QSTR);
    conv_w_t<<<dim3(KSTR / 32, HIDDEN / 32), 256>>>(wk, wkh, wkl, HIDDEN, KSTR);
    conv_w_t<<<dim3(KSTR / 32, HIDDEN / 32), 256>>>(wv, wvh, wvl, HIDDEN, KSTR);
    conv_w_t<<<dim3(HIDDEN / 32, QSTR / 32), 256>>>(wo, woh, wol, QSTR, HIDDEN);

    // 1-3) QKV projections (HMMA bf16x3)
    gemm_bf16x3<<<dim3(QSTR / 128, S_LEN / 128), 256, G_SMEM>>>(
        hsh, hsl, wqh, wql, qp, S_LEN, QSTR, HIDDEN);
    gemm_bf16x3<<<dim3(KSTR / 128, S_LEN / 128), 256, G_SMEM>>>(
        hsh, hsl, wkh, wkl, kp, S_LEN, KSTR, HIDDEN);
    gemm_bf16x3<<<dim3(KSTR / 128, S_LEN / 128), 256, G_SMEM>>>(
        hsh, hsl, wvh, wvl, vp, S_LEN, KSTR, HIDDEN);

    // 4-5) RMSNorm + RoPE (score scale folded into Q)
    rmsnorm_rope<<<dim3(S_LEN, HQ), 128>>>(qp, cosp, sinp, qnw, QSTR, SM_SCALE);
    rmsnorm_rope<<<dim3(S_LEN, HKV), 128>>>(kp, cosp, sinp, knw, KSTR, 1.0f);

    // 6) causal flash attention (fp32)
    flash_attn<<<dim3(S_LEN / BM, HQ), 256, FA_SMEM>>>(qp, kp, vp, ap);

    // 7) output projection (HMMA bf16x3)
    conv_split<<<(S_LEN * QSTR) / 1024, 256>>>(ap, ath, atl);
    gemm_bf16x3<<<dim3(HIDDEN / 128, S_LEN / 128), 256, G_SMEM>>>(
        ath, atl, woh, wol, out, S_LEN, HIDDEN, QSTR);
}

// round 4
// speedup vs baseline: 3.9954x; 3.1504x over previous
#include <cuda_runtime.h>
#include <cuda_bf16.h>
#include <math.h>
#include <stdint.h>

#define S_LEN 4096
#define HIDDEN 2048
#define HQ 16
#define HKV 4
#define DHD 128
#define QSTR (HQ*DHD)    // 2048
#define KSTR (HKV*DHD)   // 512
#define RMS_EPS 1e-6f
#define SM_SCALE 0.08838834764831845f  // 128^-0.5

// ------------------------- scratch (static device globals) ----------------------
__device__ float g_q[S_LEN * QSTR];
__device__ float g_k[S_LEN * KSTR];
__device__ float g_v[S_LEN * KSTR];

// bf16 split buffers
__device__ __nv_bfloat16 g_hs_h[S_LEN * HIDDEN];
__device__ __nv_bfloat16 g_hs_l[S_LEN * HIDDEN];
__device__ __nv_bfloat16 g_at_h[S_LEN * QSTR];
__device__ __nv_bfloat16 g_at_l[S_LEN * QSTR];
// q/k (post norm+rope) and v^T bf16 splits
__device__ __nv_bfloat16 g_qh[S_LEN * QSTR];
__device__ __nv_bfloat16 g_ql[S_LEN * QSTR];
__device__ __nv_bfloat16 g_kh[S_LEN * KSTR];
__device__ __nv_bfloat16 g_kl[S_LEN * KSTR];
__device__ __nv_bfloat16 g_vth[KSTR * S_LEN];   // [hk*128+d][s]
__device__ __nv_bfloat16 g_vtl[KSTR * S_LEN];
// transposed weights [N, K]
__device__ __nv_bfloat16 g_wq_h[QSTR * HIDDEN];
__device__ __nv_bfloat16 g_wq_l[QSTR * HIDDEN];
__device__ __nv_bfloat16 g_wk_h[KSTR * HIDDEN];
__device__ __nv_bfloat16 g_wk_l[KSTR * HIDDEN];
__device__ __nv_bfloat16 g_wv_h[KSTR * HIDDEN];
__device__ __nv_bfloat16 g_wv_l[KSTR * HIDDEN];
__device__ __nv_bfloat16 g_wo_h[HIDDEN * QSTR];
__device__ __nv_bfloat16 g_wo_l[HIDDEN * QSTR];

// ------------------------- helpers ----------------------------------------------
__device__ __forceinline__ uint32_t smem_u32(const void* p) {
    uint32_t a;
    asm("{ .reg .u64 t; cvta.to.shared.u64 t, %1; cvt.u32.u64 %0, t; }" : "=r"(a) : "l"(p));
    return a;
}
__device__ __forceinline__ void ldsm_x4(uint32_t* r, uint32_t addr) {
    asm volatile("ldmatrix.sync.aligned.m8n8.x4.shared.b16 {%0,%1,%2,%3}, [%4];"
                 : "=r"(r[0]), "=r"(r[1]), "=r"(r[2]), "=r"(r[3]) : "r"(addr));
}
__device__ __forceinline__ void mma_bf16(float* d, const uint32_t* a, const uint32_t* b,
                                         const float* c) {
    asm volatile(
        "mma.sync.aligned.m16n8k16.row.col.f32.bf16.bf16.f32 "
        "{%0,%1,%2,%3}, {%4,%5,%6,%7}, {%8,%9}, {%10,%11,%12,%13};"
        : "=f"(d[0]), "=f"(d[1]), "=f"(d[2]), "=f"(d[3])
        : "r"(a[0]), "r"(a[1]), "r"(a[2]), "r"(a[3]),
          "r"(b[0]), "r"(b[1]),
          "f"(c[0]), "f"(c[1]), "f"(c[2]), "f"(c[3]));
}
__device__ __forceinline__ void cp_async16(uint32_t dst, const void* src) {
    asm volatile("cp.async.cg.shared.global [%0], [%1], 16;" :: "r"(dst), "l"(src) : "memory");
}
__device__ __forceinline__ void cp_commit() {
    asm volatile("cp.async.commit_group;" ::: "memory");
}
// logical tile rows of 64B (32 bf16) with XOR swizzle for conflict-free ldmatrix
__device__ __forceinline__ uint32_t swz(uint32_t tileBase, int r, int c) {
    uint32_t off = r * 64 + c * 16;
    off ^= ((off >> 7) & 7) << 4;
    return tileBase + off;
}

// ------------------------- fp32 -> bf16 hi/lo split ------------------------------
__global__ __launch_bounds__(256) void conv_split(
    const float* __restrict__ X, __nv_bfloat16* __restrict__ H,
    __nv_bfloat16* __restrict__ L)
{
    int i = (blockIdx.x * 256 + threadIdx.x) * 4;
    float4 v = *(const float4*)(X + i);
    __nv_bfloat16 h0 = __float2bfloat16(v.x), h1 = __float2bfloat16(v.y);
    __nv_bfloat16 h2 = __float2bfloat16(v.z), h3 = __float2bfloat16(v.w);
    __nv_bfloat16 l0 = __float2bfloat16(v.x - __bfloat162float(h0));
    __nv_bfloat16 l1 = __float2bfloat16(v.y - __bfloat162float(h1));
    __nv_bfloat16 l2 = __float2bfloat16(v.z - __bfloat162float(h2));
    __nv_bfloat16 l3 = __float2bfloat16(v.w - __bfloat162float(h3));
    *(__nv_bfloat162*)(H + i)     = __halves2bfloat162(h0, h1);
    *(__nv_bfloat162*)(H + i + 2) = __halves2bfloat162(h2, h3);
    *(__nv_bfloat162*)(L + i)     = __halves2bfloat162(l0, l1);
    *(__nv_bfloat162*)(L + i + 2) = __halves2bfloat162(l2, l3);
}

// ------------------------- fp32 [K,N] -> bf16 hi/lo transposed [N,K] -------------
__global__ __launch_bounds__(256) void conv_w_t(
    const float* __restrict__ W, __nv_bfloat16* __restrict__ Th,
    __nv_bfloat16* __restrict__ Tl, int K, int N)
{
    __shared__ float t[32][33];
    int n0 = blockIdx.x * 32, k0 = blockIdx.y * 32;
    int tx = threadIdx.x & 31, ty = threadIdx.x >> 5;  // 32 x 8
#pragma unroll
    for (int j = 0; j < 4; j++)
        t[ty + 8 * j][tx] = W[(size_t)(k0 + ty + 8 * j) * N + n0 + tx];
    __syncthreads();
#pragma unroll
    for (int j = 0; j < 4; j++) {
        float v = t[tx][ty + 8 * j];
        __nv_bfloat16 h = __float2bfloat16(v);
        size_t o = (size_t)(n0 + ty + 8 * j) * K + k0 + tx;
        Th[o] = h;
        Tl[o] = __float2bfloat16(v - __bfloat162float(h));
    }
}

// ------------------------- bf16x3 HMMA GEMM --------------------------------------
#define GT_BYTES 8192
#define GSTAGE   (4 * GT_BYTES)
#define G_SMEM   (2 * GSTAGE)

__global__ __launch_bounds__(256) void gemm_bf16x3(
    const __nv_bfloat16* __restrict__ Ah, const __nv_bfloat16* __restrict__ Al,
    const __nv_bfloat16* __restrict__ Bh, const __nv_bfloat16* __restrict__ Bl,
    float* __restrict__ C, int M, int N, int K)
{
    extern __shared__ char smc[];
    const uint32_t sb = smem_u32(smc);
    const int tid  = threadIdx.x;
    const int wid  = tid >> 5;
    const int lane = tid & 31;
    const int m0 = blockIdx.y * 128, n0 = blockIdx.x * 128;
    const int mBase = (wid >> 1) * 32;
    const int nBase = (wid & 1) * 64;

    const __nv_bfloat16* srcs[4] = {Ah + (size_t)m0 * K, Al + (size_t)m0 * K,
                                    Bh + (size_t)n0 * K, Bl + (size_t)n0 * K};

    float acc[2][8][4];
#pragma unroll
    for (int f = 0; f < 2; f++)
#pragma unroll
        for (int j = 0; j < 8; j++)
#pragma unroll
            for (int x = 0; x < 4; x++) acc[f][j][x] = 0.f;

    const int nChunks = K >> 5;
    {
#pragma unroll
        for (int s = 0; s < 8; s++) {
            int i = tid + 256 * s;
            int tile = i >> 9, r = (i >> 2) & 127, c = i & 3;
            cp_async16(swz(sb + tile * GT_BYTES, r, c),
                       srcs[tile] + (size_t)r * K + c * 8);
        }
        cp_commit();
    }

    const int lr = lane & 15, lc = lane >> 4;

    for (int kc = 0; kc < nChunks; kc++) {
        const uint32_t st = sb + (kc & 1) * GSTAGE;
        if (kc + 1 < nChunks) {
            const int k0 = (kc + 1) << 5;
            const uint32_t stn = sb + ((kc + 1) & 1) * GSTAGE;
#pragma unroll
            for (int s = 0; s < 8; s++) {
                int i = tid + 256 * s;
                int tile = i >> 9, r = (i >> 2) & 127, c = i & 3;
                cp_async16(swz(stn + tile * GT_BYTES, r, c),
                           srcs[tile] + (size_t)r * K + k0 + c * 8);
            }
            cp_commit();
            asm volatile("cp.async.wait_group 1;" ::: "memory");
        } else {
            asm volatile("cp.async.wait_group 0;" ::: "memory");
        }
        __syncthreads();

        const uint32_t tAh = st, tAl = st + GT_BYTES;
        const uint32_t tBh = st + 2 * GT_BYTES, tBl = st + 3 * GT_BYTES;

#pragma unroll
        for (int ks = 0; ks < 2; ks++) {
            const int ch = ks * 2 + lc;
            uint32_t ah[2][4], al[2][4], bb[4][4];
#pragma unroll
            for (int f = 0; f < 2; f++)
                ldsm_x4(ah[f], swz(tAh, mBase + f * 16 + lr, ch));
#pragma unroll
            for (int g = 0; g < 4; g++)
                ldsm_x4(bb[g], swz(tBh, nBase + g * 16 + lr, ch));
#pragma unroll
            for (int f = 0; f < 2; f++)
#pragma unroll
                for (int j = 0; j < 8; j++) {
                    uint32_t bfr[2] = {bb[j >> 1][j & 1], bb[j >> 1][2 + (j & 1)]};
                    mma_bf16(acc[f][j], ah[f], bfr, acc[f][j]);
                }
#pragma unroll
            for (int f = 0; f < 2; f++)
                ldsm_x4(al[f], swz(tAl, mBase + f * 16 + lr, ch));
#pragma unroll
            for (int f = 0; f < 2; f++)
#pragma unroll
                for (int j = 0; j < 8; j++) {
                    uint32_t bfr[2] = {bb[j >> 1][j & 1], bb[j >> 1][2 + (j & 1)]};
                    mma_bf16(acc[f][j], al[f], bfr, acc[f][j]);
                }
#pragma unroll
            for (int g = 0; g < 4; g++)
                ldsm_x4(bb[g], swz(tBl, nBase + g * 16 + lr, ch));
#pragma unroll
            for (int f = 0; f < 2; f++)
#pragma unroll
                for (int j = 0; j < 8; j++) {
                    uint32_t bfr[2] = {bb[j >> 1][j & 1], bb[j >> 1][2 + (j & 1)]};
                    mma_bf16(acc[f][j], ah[f], bfr, acc[f][j]);
                }
        }
        __syncthreads();
    }

    const int erow = lane >> 2;
    const int ecol = (lane & 3) * 2;
#pragma unroll
    for (int f = 0; f < 2; f++) {
        int rg = m0 + mBase + f * 16 + erow;
#pragma unroll
        for (int j = 0; j < 8; j++) {
            int cg = n0 + nBase + j * 8 + ecol;
            *(float2*)(C + (size_t)rg * N + cg)       = make_float2(acc[f][j][0], acc[f][j][1]);
            *(float2*)(C + (size_t)(rg + 8) * N + cg) = make_float2(acc[f][j][2], acc[f][j][3]);
        }
    }
}

// ------------------------- fused RMSNorm + RoPE -> bf16 hi/lo --------------------
__global__ __launch_bounds__(128) void rms_rope_split(
    const float* __restrict__ in, const float* __restrict__ cosp,
    const float* __restrict__ sinp, const float* __restrict__ w,
    int nh, float outScale,
    __nv_bfloat16* __restrict__ Hh, __nv_bfloat16* __restrict__ Hl)
{
    const int s = blockIdx.x;
    const int h = blockIdx.y;
    const int d = threadIdx.x;

    const float* x = in + ((size_t)s * nh + h) * DHD;
    float v = x[d];

    __shared__ float red[128];
    red[d] = v * v;
    __syncthreads();
#pragma unroll
    for (int off = 64; off > 0; off >>= 1) {
        if (d < off) red[d] += red[d + off];
        __syncthreads();
    }
    float inv = rsqrtf(red[0] * (1.0f / DHD) + RMS_EPS);

    const int dp = (d < 64) ? d + 64 : d - 64;
    float vp  = x[dp];
    float xn  = v  * inv * w[d];
    float xpn = vp * inv * w[dp];
    float c  = cosp[s * DHD + d];
    float sn = sinp[s * DHD + d];
    float rot = (d < 64) ? -xpn : xpn;
    float out = (xn * c + rot * sn) * outScale;

    size_t o = ((size_t)s * nh + h) * DHD + d;
    __nv_bfloat16 hh = __float2bfloat16(out);
    Hh[o] = hh;
    Hl[o] = __float2bfloat16(out - __bfloat162float(hh));
}

// ------------------------- HMMA causal flash attention ---------------------------
// CTA: 64 queries x 1 head, 4 warps (16 rows each). bf16x3 for QK^T and PV.
#define FBM 64
#define FBN 64
#define FQ_OFF 0
#define FK_OFF 32768
#define FV_OFF 65536
#define F_SMEM 98304

__device__ __forceinline__ void flash_load_kv(
    uint32_t sb, int tid, int kg0, int hk,
    const __nv_bfloat16* Kh, const __nv_bfloat16* Kl,
    const __nv_bfloat16* Vth, const __nv_bfloat16* Vtl)
{
    const __nv_bfloat16* Ks[2] = {Kh, Kl};
    const __nv_bfloat16* Vs[2] = {Vth, Vtl};
#pragma unroll
    for (int s = 0; s < 16; s++) {
        int i = tid + 128 * s;
        int sp = i >> 10, c = (i >> 8) & 3, r = (i >> 2) & 63, x = i & 3;
        cp_async16(swz(sb + FK_OFF + sp * 16384 + c * 4096, r, x),
                   Ks[sp] + ((size_t)(kg0 + r) * HKV + hk) * DHD + c * 32 + x * 8);
    }
#pragma unroll
    for (int s = 0; s < 16; s++) {
        int i = tid + 128 * s;
        int sp = i >> 10, kc = (i >> 9) & 1, r = (i >> 2) & 127, x = i & 3;
        cp_async16(swz(sb + FV_OFF + sp * 16384 + kc * 8192, r, x),
                   Vs[sp] + (size_t)(hk * DHD + r) * S_LEN + kg0 + kc * 32 + x * 8);
    }
    cp_commit();
}

__global__ __launch_bounds__(128) void flash_hmma(
    const __nv_bfloat16* __restrict__ Qh, const __nv_bfloat16* __restrict__ Ql,
    const __nv_bfloat16* __restrict__ Kh, const __nv_bfloat16* __restrict__ Kl,
    const __nv_bfloat16* __restrict__ Vth, const __nv_bfloat16* __restrict__ Vtl,
    __nv_bfloat16* __restrict__ Oh, __nv_bfloat16* __restrict__ Ol)
{
    extern __shared__ char smf[];
    const uint32_t sb = smem_u32(smf);
    const int tid = threadIdx.x, wid = tid >> 5, lane = tid & 31;
    const int qt = (int)gridDim.x - 1 - (int)blockIdx.x;   // heavy tiles first
    const int h = blockIdx.y, hk = h >> 2;
    const int qm0 = qt * FBM;
    const int wBase = wid * 16;
    const int lr = lane & 15, lc = lane >> 4;
    const int erow = lane >> 2, q4 = lane & 3;

    // stage Q tile (hi/lo)
    const __nv_bfloat16* Qs[2] = {Qh, Ql};
#pragma unroll
    for (int s = 0; s < 16; s++) {
        int i = tid + 128 * s;
        int sp = i >> 10, c = (i >> 8) & 3, r = (i >> 2) & 63, x = i & 3;
        cp_async16(swz(sb + FQ_OFF + sp * 16384 + c * 4096, r, x),
                   Qs[sp] + ((size_t)(qm0 + r) * HQ + h) * DHD + c * 32 + x * 8);
    }
    flash_load_kv(sb, tid, 0, hk, Kh, Kl, Vth, Vtl);
    asm volatile("cp.async.wait_group 0;" ::: "memory");
    __syncthreads();

    // Q fragments in registers (invariant over key tiles)
    uint32_t qfh[8][4], qfl[8][4];
#pragma unroll
    for (int kk = 0; kk < 8; kk++) {
        int c = kk >> 1, x = (kk & 1) * 2 + lc;
        ldsm_x4(qfh[kk], swz(sb + FQ_OFF + c * 4096, wBase + lr, x));
        ldsm_x4(qfl[kk], swz(sb + FQ_OFF + 16384 + c * 4096, wBase + lr, x));
    }

    float oacc[16][4];
#pragma unroll
    for (int jj = 0; jj < 16; jj++)
#pragma unroll
        for (int x = 0; x < 4; x++) oacc[jj][x] = 0.f;
    float m0 = -1e30f, m1 = -1e30f, l0 = 0.f, l1 = 0.f;

    for (int t = 0; t <= qt; t++) {
        // ---- S = Q @ K^T (bf16x3)
        float sacc[8][4];
#pragma unroll
        for (int j = 0; j < 8; j++)
#pragma unroll
            for (int x = 0; x < 4; x++) sacc[j][x] = 0.f;

#pragma unroll
        for (int kk = 0; kk < 8; kk++) {
            int c = kk >> 1, x = (kk & 1) * 2 + lc;
            uint32_t kb[4][4];
#pragma unroll
            for (int g = 0; g < 4; g++)
                ldsm_x4(kb[g], swz(sb + FK_OFF + c * 4096, g * 16 + lr, x));
#pragma unroll
            for (int j = 0; j < 8; j++) {
                uint32_t bf[2] = {kb[j >> 1][j & 1], kb[j >> 1][(j & 1) + 2]};
                mma_bf16(sacc[j], qfh[kk], bf, sacc[j]);
            }
#pragma unroll
            for (int j = 0; j < 8; j++) {
                uint32_t bf[2] = {kb[j >> 1][j & 1], kb[j >> 1][(j & 1) + 2]};
                mma_bf16(sacc[j], qfl[kk], bf, sacc[j]);
            }
#pragma unroll
            for (int g = 0; g < 4; g++)
                ldsm_x4(kb[g], swz(sb + FK_OFF + 16384 + c * 4096, g * 16 + lr, x));
#pragma unroll
            for (int j = 0; j < 8; j++) {
                uint32_t bf[2] = {kb[j >> 1][j & 1], kb[j >> 1][(j & 1) + 2]};
                mma_bf16(sacc[j], qfh[kk], bf, sacc[j]);
            }
        }

        // ---- causal mask (diagonal tile only)
        if (t == qt) {
            int row0 = qm0 + wBase + erow, row1 = row0 + 8;
            int colb = t * FBN + q4 * 2;
#pragma unroll
            for (int j = 0; j < 8; j++) {
                int c0 = colb + j * 8, c1 = c0 + 1;
                if (c0 > row0) sacc[j][0] = -1e30f;
                if (c1 > row0) sacc[j][1] = -1e30f;
                if (c0 > row1) sacc[j][2] = -1e30f;
                if (c1 > row1) sacc[j][3] = -1e30f;
            }
        }

        // ---- online softmax in registers
        float mx0 = -1e30f, mx1 = -1e30f;
#pragma unroll
        for (int j = 0; j < 8; j++) {
            mx0 = fmaxf(mx0, fmaxf(sacc[j][0], sacc[j][1]));
            mx1 = fmaxf(mx1, fmaxf(sacc[j][2], sacc[j][3]));
        }
        mx0 = fmaxf(mx0, __shfl_xor_sync(0xFFFFFFFFu, mx0, 1));
        mx0 = fmaxf(mx0, __shfl_xor_sync(0xFFFFFFFFu, mx0, 2));
        mx1 = fmaxf(mx1, __shfl_xor_sync(0xFFFFFFFFu, mx1, 1));
        mx1 = fmaxf(mx1, __shfl_xor_sync(0xFFFFFFFFu, mx1, 2));
        float mn0 = fmaxf(m0, mx0), mn1 = fmaxf(m1, mx1);
        float a0 = __expf(m0 - mn0), a1 = __expf(m1 - mn1);
        float s0 = 0.f, s1 = 0.f;
#pragma unroll
        for (int j = 0; j < 8; j++) {
            float p0 = __expf(sacc[j][0] - mn0); sacc[j][0] = p0; s0 += p0;
            float p1 = __expf(sacc[j][1] - mn0); sacc[j][1] = p1; s0 += p1;
            float p2 = __expf(sacc[j][2] - mn1); sacc[j][2] = p2; s1 += p2;
            float p3 = __expf(sacc[j][3] - mn1); sacc[j][3] = p3; s1 += p3;
        }
        s0 += __shfl_xor_sync(0xFFFFFFFFu, s0, 1);
        s0 += __shfl_xor_sync(0xFFFFFFFFu, s0, 2);
        s1 += __shfl_xor_sync(0xFFFFFFFFu, s1, 1);
        s1 += __shfl_xor_sync(0xFFFFFFFFu, s1, 2);
        l0 = l0 * a0 + s0;
        l1 = l1 * a1 + s1;
        m0 = mn0; m1 = mn1;
#pragma unroll
        for (int jj = 0; jj < 16; jj++) {
            oacc[jj][0] *= a0; oacc[jj][1] *= a0;
            oacc[jj][2] *= a1; oacc[jj][3] *= a1;
        }

        // ---- O += P @ V (bf16x3, P frags packed from registers)
#pragma unroll
        for (int tt = 0; tt < 4; tt++) {
            uint32_t ph[4], pl[4];
            {
                __nv_bfloat162 v0 = __floats2bfloat162_rn(sacc[2*tt][0],   sacc[2*tt][1]);
                __nv_bfloat162 v1 = __floats2bfloat162_rn(sacc[2*tt][2],   sacc[2*tt][3]);
                __nv_bfloat162 v2 = __floats2bfloat162_rn(sacc[2*tt+1][0], sacc[2*tt+1][1]);
                __nv_bfloat162 v3 = __floats2bfloat162_rn(sacc[2*tt+1][2], sacc[2*tt+1][3]);
                ph[0] = *(uint32_t*)&v0; ph[1] = *(uint32_t*)&v1;
                ph[2] = *(uint32_t*)&v2; ph[3] = *(uint32_t*)&v3;
                __nv_bfloat162 w0 = __floats2bfloat162_rn(
                    sacc[2*tt][0]   - __bfloat162float(v0.x), sacc[2*tt][1]   - __bfloat162float(v0.y));
                __nv_bfloat162 w1 = __floats2bfloat162_rn(
                    sacc[2*tt][2]   - __bfloat162float(v1.x), sacc[2*tt][3]   - __bfloat162float(v1.y));
                __nv_bfloat162 w2 = __floats2bfloat162_rn(
                    sacc[2*tt+1][0] - __bfloat162float(v2.x), sacc[2*tt+1][1] - __bfloat162float(v2.y));
                __nv_bfloat162 w3 = __floats2bfloat162_rn(
                    sacc[2*tt+1][2] - __bfloat162float(v3.x), sacc[2*tt+1][3] - __bfloat162float(v3.y));
                pl[0] = *(uint32_t*)&w0; pl[1] = *(uint32_t*)&w1;
                pl[2] = *(uint32_t*)&w2; pl[3] = *(uint32_t*)&w3;
            }
            int kc = tt >> 1, x = (tt & 1) * 2 + lc;
            uint32_t vb[8][4];
#pragma unroll
            for (int g = 0; g < 8; g++)
                ldsm_x4(vb[g], swz(sb + FV_OFF + kc * 8192, g * 16 + lr, x));
#pragma unroll
            for (int jj = 0; jj < 16; jj++) {
                uint32_t bf[2] = {vb[jj >> 1][jj & 1], vb[jj >> 1][(jj & 1) + 2]};
                mma_bf16(oacc[jj], ph, bf, oacc[jj]);
            }
#pragma unroll
            for (int jj = 0; jj < 16; jj++) {
                uint32_t bf[2] = {vb[jj >> 1][jj & 1], vb[jj >> 1][(jj & 1) + 2]};
                mma_bf16(oacc[jj], pl, bf, oacc[jj]);
            }
#pragma unroll
            for (int g = 0; g < 8; g++)
                ldsm_x4(vb[g], swz(sb + FV_OFF + 16384 + kc * 8192, g * 16 + lr, x));
#pragma unroll
            for (int jj = 0; jj < 16; jj++) {
                uint32_t bf[2] = {vb[jj >> 1][jj & 1], vb[jj >> 1][(jj & 1) + 2]};
                mma_bf16(oacc[jj], ph, bf, oacc[jj]);
            }
        }

        __syncthreads();
        if (t < qt) {
            flash_load_kv(sb, tid, (t + 1) * FBN, hk, Kh, Kl, Vth, Vtl);
            asm volatile("cp.async.wait_group 0;" ::: "memory");
            __syncthreads();
        }
    }

    // ---- epilogue: divide by l, split to bf16 hi/lo, store
    float il0 = 1.0f / l0, il1 = 1.0f / l1;
    int row0 = qm0 + wBase + erow;
#pragma unroll
    for (int jj = 0; jj < 16; jj++) {
        int col = jj * 8 + q4 * 2;
        {
            float o0 = oacc[jj][0] * il0, o1 = oacc[jj][1] * il0;
            __nv_bfloat162 hh = __floats2bfloat162_rn(o0, o1);
            __nv_bfloat162 ll = __floats2bfloat162_rn(o0 - __bfloat162float(hh.x),
                                                      o1 - __bfloat162float(hh.y));
            size_t off = (size_t)row0 * QSTR + h * DHD + col;
            *(__nv_bfloat162*)(Oh + off) = hh;
            *(__nv_bfloat162*)(Ol + off) = ll;
        }
        {
            float o0 = oacc[jj][2] * il1, o1 = oacc[jj][3] * il1;
            __nv_bfloat162 hh = __floats2bfloat162_rn(o0, o1);
            __nv_bfloat162 ll = __floats2bfloat162_rn(o0 - __bfloat162float(hh.x),
                                                      o1 - __bfloat162float(hh.y));
            size_t off = (size_t)(row0 + 8) * QSTR + h * DHD + col;
            *(__nv_bfloat162*)(Oh + off) = hh;
            *(__nv_bfloat162*)(Ol + off) = ll;
        }
    }
}

// ------------------------- launch -----------------------------------------------
extern "C" void kernel_launch(void* const* d_in, const int* in_sizes, int n_in,
                              void* d_out, int out_size)
{
    (void)in_sizes; (void)n_in; (void)out_size;
    const float* hs   = (const float*)d_in[0];
    const float* cosp = (const float*)d_in[1];
    const float* sinp = (const float*)d_in[2];
    const float* wq   = (const float*)d_in[3];
    const float* wk   = (const float*)d_in[4];
    const float* wv   = (const float*)d_in[5];
    const float* wo   = (const float*)d_in[6];
    const float* qnw  = (const float*)d_in[7];
    const float* knw  = (const float*)d_in[8];
    float* out = (float*)d_out;

    float *qp, *kp, *vp;
    cudaGetSymbolAddress((void**)&qp, g_q);
    cudaGetSymbolAddress((void**)&kp, g_k);
    cudaGetSymbolAddress((void**)&vp, g_v);
    __nv_bfloat16 *hsh, *hsl, *ath, *atl;
    __nv_bfloat16 *qh, *ql, *kh, *kl, *vth, *vtl;
    __nv_bfloat16 *wqh, *wql, *wkh, *wkl, *wvh, *wvl, *woh, *wol;
    cudaGetSymbolAddress((void**)&hsh, g_hs_h);
    cudaGetSymbolAddress((void**)&hsl, g_hs_l);
    cudaGetSymbolAddress((void**)&ath, g_at_h);
    cudaGetSymbolAddress((void**)&atl, g_at_l);
    cudaGetSymbolAddress((void**)&qh, g_qh);
    cudaGetSymbolAddress((void**)&ql, g_ql);
    cudaGetSymbolAddress((void**)&kh, g_kh);
    cudaGetSymbolAddress((void**)&kl, g_kl);
    cudaGetSymbolAddress((void**)&vth, g_vth);
    cudaGetSymbolAddress((void**)&vtl, g_vtl);
    cudaGetSymbolAddress((void**)&wqh, g_wq_h);
    cudaGetSymbolAddress((void**)&wql, g_wq_l);
    cudaGetSymbolAddress((void**)&wkh, g_wk_h);
    cudaGetSymbolAddress((void**)&wkl, g_wk_l);
    cudaGetSymbolAddress((void**)&wvh, g_wv_h);
    cudaGetSymbolAddress((void**)&wvl, g_wv_l);
    cudaGetSymbolAddress((void**)&woh, g_wo_h);
    cudaGetSymbolAddress((void**)&wol, g_wo_l);

    cudaFuncSetAttribute(gemm_bf16x3, cudaFuncAttributeMaxDynamicSharedMemorySize, G_SMEM);
    cudaFuncSetAttribute(flash_hmma, cudaFuncAttributeMaxDynamicSharedMemorySize, F_SMEM);

    // 0) precision splits + weight transposes
    conv_split<<<(S_LEN * HIDDEN) / 1024, 256>>>(hs, hsh, hsl);
    conv_w_t<<<dim3(QSTR / 32, HIDDEN / 32), 256>>>(wq, wqh, wql, HIDDEN, QSTR);
    conv_w_t<<<dim3(KSTR / 32, HIDDEN / 32), 256>>>(wk, wkh, wkl, HIDDEN, KSTR);
    conv_w_t<<<dim3(KSTR / 32, HIDDEN / 32), 256>>>(wv, wvh, wvl, HIDDEN, KSTR);
    conv_w_t<<<dim3(HIDDEN / 32, QSTR / 32), 256>>>(wo, woh, wol, QSTR, HIDDEN);

    // 1-3) QKV projections (HMMA bf16x3)
    gemm_bf16x3<<<dim3(QSTR / 128, S_LEN / 128), 256, G_SMEM>>>(
        hsh, hsl, wqh, wql, qp, S_LEN, QSTR, HIDDEN);
    gemm_bf16x3<<<dim3(KSTR / 128, S_LEN / 128), 256, G_SMEM>>>(
        hsh, hsl, wkh, wkl, kp, S_LEN, KSTR, HIDDEN);
    gemm_bf16x3<<<dim3(KSTR / 128, S_LEN / 128), 256, G_SMEM>>>(
        hsh, hsl, wvh, wvl, vp, S_LEN, KSTR, HIDDEN);

    // 4-6) RMSNorm + RoPE -> bf16 splits ; V -> transposed bf16 splits
    rms_rope_split<<<dim3(S_LEN, HQ), 128>>>(qp, cosp, sinp, qnw, HQ, SM_SCALE, qh, ql);
    rms_rope_split<<<dim3(S_LEN, HKV), 128>>>(kp, cosp, sinp, knw, HKV, 1.0f, kh, kl);
    conv_w_t<<<dim3(KSTR / 32, S_LEN / 32), 256>>>(vp, vth, vtl, S_LEN, KSTR);

    // 7) causal flash attention (HMMA bf16x3) -> attn splits
    flash_hmma<<<dim3(S_LEN / FBM, HQ), 128, F_SMEM>>>(
        qh, ql, kh, kl, vth, vtl, ath, atl);

    // 8) output projection (HMMA bf16x3)
    gemm_bf16x3<<<dim3(HIDDEN / 128, S_LEN / 128), 256, G_SMEM>>>(
        ath, atl, woh, wol, out, S_LEN, HIDDEN, QSTR);
}